// round 2
// baseline (speedup 1.0000x reference)
#include <cuda_runtime.h>

// Shapes
#define S    112
#define SP   113           // padded pitch for conflict-free strided smem reads
#define TS   7             // per-thread register tile (7x7), 16x16 threads cover 112x112
#define NB   64            // batches
#define NC   64            // channels (= groups)
#define PLANE (S * S)      // 12544 floats per plane

// Only channels 0 and 1 have any kept mask entries:
//   xs[i] = i ^ 2 (bitwise), s = xs[i] + xs[j] <= 218, mul = 14
//   c==0 keeps s < 196 ; c==1 keeps s >= 196 ; c>=2 keeps nothing.

// ---------------------------------------------------------------------------
// Fill channels [2, 64) with 1e-8 using 128-bit stores.
// grid = (GX, 64): blockIdx.y = batch, x-dim grid-strides over the 62-plane slab.
// ---------------------------------------------------------------------------
__global__ void fill_kernel(float4* __restrict__ out4) {
    const int b = blockIdx.y;
    // per-batch slab: planes 2..63 are contiguous: 62 * (12544/4) float4
    const int n = 62 * (PLANE / 4);
    float4* base = out4 + (size_t)b * (NC * (PLANE / 4)) + 2 * (PLANE / 4);
    const float v = 1e-8f;
    const float4 f = make_float4(v, v, v, v);
    const int stride = gridDim.x * blockDim.x;
    for (int i = blockIdx.x * blockDim.x + threadIdx.x; i < n; i += stride) {
        base[i] = f;
    }
}

// ---------------------------------------------------------------------------
// DCT for channels 0 and 1: Y = W @ X @ W^T, then masked select vs 1e-8.
// One block per (c, b). 256 threads, 7x7 register tile each.
// smem: sW [S][SP], sX [S][S], sT [S][SP]  -> 151,424 bytes (dynamic).
// ---------------------------------------------------------------------------
__global__ void dct_kernel(const float* __restrict__ x,
                           const float* __restrict__ W,
                           float* __restrict__ out) {
    extern __shared__ float sm[];
    float* sW = sm;                 // S * SP
    float* sX = sW + S * SP;        // S * S
    float* sT = sX + S * S;         // S * SP

    const int c   = blockIdx.x;     // 0 or 1
    const int b   = blockIdx.y;     // 0..63
    const int tid = threadIdx.x;    // 0..255
    const int tx  = tid & 15;       // column tile index
    const int ty  = tid >> 4;       // row tile index
    const int i0  = ty * TS;
    const int j0  = tx * TS;

    // Load W into padded smem
    for (int idx = tid; idx < S * S; idx += 256) {
        const int r  = idx / S;
        const int cc = idx - r * S;
        sW[r * SP + cc] = W[idx];
    }
    // Load X plane (contiguous) via float4
    {
        const float4* xsrc = (const float4*)(x + (size_t)(b * NC + c) * PLANE);
        float4* xdst = (float4*)sX;
        for (int idx = tid; idx < PLANE / 4; idx += 256) xdst[idx] = xsrc[idx];
    }
    __syncthreads();

    // ---------------- GEMM1: T[i][j] = sum_k W[i][k] * X[k][j] ----------------
    {
        float acc[TS][TS];
        #pragma unroll
        for (int r = 0; r < TS; r++)
            #pragma unroll
            for (int q = 0; q < TS; q++) acc[r][q] = 0.0f;

        for (int k = 0; k < S; k++) {
            float a[TS], bb[TS];
            #pragma unroll
            for (int r = 0; r < TS; r++) a[r] = sW[(i0 + r) * SP + k];   // broadcast
            #pragma unroll
            for (int q = 0; q < TS; q++) bb[q] = sX[k * S + j0 + q];     // conflict-free
            #pragma unroll
            for (int r = 0; r < TS; r++)
                #pragma unroll
                for (int q = 0; q < TS; q++)
                    acc[r][q] = fmaf(a[r], bb[q], acc[r][q]);
        }
        #pragma unroll
        for (int r = 0; r < TS; r++)
            #pragma unroll
            for (int q = 0; q < TS; q++)
                sT[(i0 + r) * SP + j0 + q] = acc[r][q];
    }
    __syncthreads();

    // ---------------- GEMM2: Y[i][j] = sum_k T[i][k] * W[j][k] ----------------
    {
        float acc[TS][TS];
        #pragma unroll
        for (int r = 0; r < TS; r++)
            #pragma unroll
            for (int q = 0; q < TS; q++) acc[r][q] = 0.0f;

        for (int k = 0; k < S; k++) {
            float a[TS], bb[TS];
            #pragma unroll
            for (int r = 0; r < TS; r++) a[r] = sT[(i0 + r) * SP + k];   // broadcast
            #pragma unroll
            for (int q = 0; q < TS; q++) bb[q] = sW[(j0 + q) * SP + k];  // pitch 113 -> conflict-free
            #pragma unroll
            for (int r = 0; r < TS; r++)
                #pragma unroll
                for (int q = 0; q < TS; q++)
                    acc[r][q] = fmaf(a[r], bb[q], acc[r][q]);
        }

        // Masked epilogue: write the full plane (kept value or 1e-8)
        float* obase = out + (size_t)(b * NC + c) * PLANE;
        #pragma unroll
        for (int r = 0; r < TS; r++) {
            const int i  = i0 + r;
            const int si = (i ^ 2);
            #pragma unroll
            for (int q = 0; q < TS; q++) {
                const int j = j0 + q;
                const int s = si + (j ^ 2);
                const bool keep = (c == 0) ? (s < 196) : (s >= 196);
                obase[i * S + j] = keep ? acc[r][q] : 1e-8f;
            }
        }
    }
}

// ---------------------------------------------------------------------------
// Launch
// ---------------------------------------------------------------------------
extern "C" void kernel_launch(void* const* d_in, const int* in_sizes, int n_in,
                              void* d_out, int out_size) {
    const float* x = (const float*)d_in[0];   // [64, 64, 112, 112]
    const float* W = (const float*)d_in[1];   // [112, 112]
    float* out = (float*)d_out;

    const int smem_bytes = (S * SP + S * S + S * SP) * (int)sizeof(float); // 151424
    cudaFuncSetAttribute(dct_kernel, cudaFuncAttributeMaxDynamicSharedMemorySize,
                         smem_bytes);

    // Fill channels 2..63 of every batch with 1e-8 (bulk of the output bytes).
    fill_kernel<<<dim3(64, NB), 256>>>((float4*)out);

    // Compute + masked-write channels 0 and 1 (128 planes total).
    dct_kernel<<<dim3(2, NB), 256, smem_bytes>>>(x, W, out);
}